// round 9
// baseline (speedup 1.0000x reference)
#include <cuda_runtime.h>
#include <cuda_fp16.h>
#include <cstdint>

// ---------------------------------------------------------------------------
// IWHT3Layer, round 9: single-barrier design.
//   CTA: 256 threads / 8 warps / 16 pixels x 64 k x 1 branch, 2 CTAs/SM.
//   Phase 1: stage ALL 16 t A-tiles (f32 LDG.128 burst, MLP=8 per thread,
//            cvt f16, STS) -> 36.9 KB smem. ONE __syncthreads.
//   Phase 2: barrier-free: warp w = n8 block, all 16 t in regs
//            (acc[16][4]); per t: 4x ldmatrix + 4x MMA + 2x LDG.128 B
//            (register double-buffered, L2-hot). Warp-staggered t order.
//   Epilogue: in-register 2D WHT butterflies + bias + float2 stores.
// ---------------------------------------------------------------------------

#define U32 unsigned int
#define U64 unsigned long long

static constexpr int PIXELS   = 12544;
static constexpr int PIX_CTA  = 16;
static constexpr int NBLK     = PIXELS / PIX_CTA;   // 784
static constexpr int T_STRIDE = PIXELS * 64;
static constexpr long long OPB = 16LL * 112 * 112 * 64;

static constexpr int A_PITCH  = 144;                 // conflict-free ldmatrix+STS
static constexpr int A_BUF    = 16 * A_PITCH;        // 2304 B per t
static constexpr int A_TOTAL  = 16 * A_BUF;          // 36864 B

// B fragments: per (branch,t,nb,lane): 4 x U64 (kc 0..3) contiguous (32B)
__device__ __align__(16) U64 g_bfrag[3 * 16 * 8 * 32 * 4];

// ---------------- helpers ----------------
__device__ __forceinline__ U32 smem_u32(const void* p) {
    U32 a; asm("{ .reg .u64 t; cvta.to.shared.u64 t, %1; cvt.u32.u64 %0, t; }"
               : "=r"(a) : "l"(p)); return a;
}
__device__ __forceinline__ void ldm4(U32& a0, U32& a1, U32& a2, U32& a3, U32 addr) {
    asm volatile("ldmatrix.sync.aligned.m8n8.x4.shared.b16 {%0,%1,%2,%3}, [%4];"
                 : "=r"(a0), "=r"(a1), "=r"(a2), "=r"(a3) : "r"(addr));
}
__device__ __forceinline__ void mma16816(float* d, U32 a0, U32 a1, U32 a2, U32 a3,
                                         U32 b0, U32 b1) {
    asm volatile("mma.sync.aligned.m16n8k16.row.col.f32.f16.f16.f32 "
                 "{%0,%1,%2,%3}, {%4,%5,%6,%7}, {%8,%9}, {%0,%1,%2,%3};"
                 : "+f"(d[0]), "+f"(d[1]), "+f"(d[2]), "+f"(d[3])
                 : "r"(a0), "r"(a1), "r"(a2), "r"(a3), "r"(b0), "r"(b1));
}
struct F2 { float x, y; };
__device__ __forceinline__ F2 f2add(F2 a, F2 b) { return {a.x + b.x, a.y + b.y}; }
__device__ __forceinline__ F2 f2sub(F2 a, F2 b) { return {a.x - b.x, a.y - b.y}; }

// ---------------- prep: build fp16 B fragments (one-time) ----------------
__global__ void wprep_kernel(const float* __restrict__ w1,
                             const float* __restrict__ w2,
                             const float* __restrict__ w3) {
    int br = blockIdx.x >> 4, t = blockIdx.x & 15;
    const float* w = (br == 0 ? w1 : (br == 1 ? w2 : w3)) + t * 4096;
    __half* frag = (__half*)g_bfrag;
    for (int idx = threadIdx.x; idx < 4096; idx += blockDim.x) {
        int c = idx >> 6, k = idx & 63;          // w[c][k], coalesced over k
        __half h = __float2half(w[idx]);
        int kc = c >> 4, cw = c & 15;
        int nb = k >> 3, lane = (k & 7) * 4 + ((cw & 7) >> 1);
        int regj = cw >> 3, hlf = cw & 1;
        size_t u64i = ((((size_t)(br * 16 + t) * 8 + nb) * 32 + lane) * 4 + kc);
        frag[u64i * 4 + regj * 2 + hlf] = h;
    }
}

// ---------------- main kernel ----------------
__global__ __launch_bounds__(256, 2)
void iwht_mma_kernel(const float* __restrict__ tr1, const float* __restrict__ tr2,
                     const float* __restrict__ tr3,
                     const float* __restrict__ b1, const float* __restrict__ b2,
                     const float* __restrict__ b3,
                     float* __restrict__ out) {
    __shared__ __align__(16) char asm_buf[A_TOTAL];   // 36864 B (16 t)

    const int tid  = threadIdx.x;
    const int lane = tid & 31;
    const int w    = tid >> 5;     // 0..7 -> n8 block (k outputs)

    const int branch = blockIdx.y;
    const float* tr   = (branch == 0 ? tr1 : (branch == 1 ? tr2 : tr3));
    const float* bias = (branch == 0 ? b1  : (branch == 1 ? b2  : b3));
    const int pix0 = blockIdx.x * PIX_CTA;

    // ---------------- phase 1: stage all 16 t ----------------
    {
        const int crow = tid >> 4, cseg = tid & 15;
        const float* xrow = tr + (size_t)(pix0 + crow) * 64 + cseg * 4;
        char* sdst = asm_buf + crow * A_PITCH + cseg * 8;
        #pragma unroll
        for (int b = 0; b < 2; b++) {
            float4 v[8];
            #pragma unroll
            for (int j = 0; j < 8; j++)
                v[j] = *(const float4*)(xrow + (size_t)(b * 8 + j) * T_STRIDE);
            #pragma unroll
            for (int j = 0; j < 8; j++) {
                __half2 h0 = __floats2half2_rn(v[j].x, v[j].y);
                __half2 h1 = __floats2half2_rn(v[j].z, v[j].w);
                *(uint2*)(sdst + (b * 8 + j) * A_BUF) =
                    make_uint2(*reinterpret_cast<U32*>(&h0),
                               *reinterpret_cast<U32*>(&h1));
            }
        }
    }
    __syncthreads();          // the ONLY barrier

    // ---------------- phase 2: barrier-free MMA loop ----------------
    const U32 sbase = smem_u32(asm_buf);
    const U32 arow0 = sbase + (U32)((lane & 15) * A_PITCH + (lane >> 4) * 16);

    const U64* gb = g_bfrag + (((size_t)branch * 16 * 8 + w) * 32 + lane) * 4;
    auto loadB = [&](int t, U64* dst) {
        const uint4* p = (const uint4*)(gb + (size_t)t * 8 * 32 * 4);
        uint4 v0 = p[0], v1 = p[1];
        dst[0] = (U64)v0.x | ((U64)v0.y << 32);
        dst[1] = (U64)v0.z | ((U64)v0.w << 32);
        dst[2] = (U64)v1.x | ((U64)v1.y << 32);
        dst[3] = (U64)v1.z | ((U64)v1.w << 32);
    };

    float acc[16][4];
    #pragma unroll
    for (int t = 0; t < 16; t++)
        #pragma unroll
        for (int i = 0; i < 4; i++) acc[t][i] = 0.0f;

    const int tstart = (2 * w) & 15;           // stagger warps across t
    U64 bcur[4], bnxt[4];
    loadB(tstart, bcur);

    #pragma unroll
    for (int i = 0; i < 16; i++) {
        const int t = (i + tstart) & 15;
        if (i < 15) loadB((t + 1) & 15, bnxt);

        const U32 ab = arow0 + (U32)(t * A_BUF);
        #pragma unroll
        for (int kc = 0; kc < 4; kc++) {
            U32 a0, a1, a2, a3;
            ldm4(a0, a1, a2, a3, ab + kc * 32);
            mma16816(acc[t], a0, a1, a2, a3,
                     (U32)bcur[kc], (U64)(bcur[kc] >> 32));
        }
        #pragma unroll
        for (int kc = 0; kc < 4; kc++) bcur[kc] = bnxt[kc];
    }

    // ---------------- epilogue: in-register 2D WHT + bias + stores ----------
    const int cl = lane & 3, rl = lane >> 2;
    float* outB = out + (size_t)branch * OPB;
    const int kst = w * 8 + cl * 2;
    const float2 bv = *(const float2*)(bias + kst);

    #pragma unroll
    for (int rh = 0; rh < 2; rh++) {
        const int P = pix0 + rh * 8 + rl;
        const int pb_ = P / 784, rr = P - pb_ * 784;
        const int ii = rr / 28, jj = rr - ii * 28;
        float* obase = outB + ((size_t)(pb_ * 112 + ii * 4) * 112 + jj * 4) * 64 + kst;

        // u-stage butterflies over t = 4u+v
        F2 U[4][4];
        #pragma unroll
        for (int v = 0; v < 4; v++) {
            F2 y0 = {acc[v][rh * 2],      acc[v][rh * 2 + 1]};
            F2 y1 = {acc[4 + v][rh * 2],  acc[4 + v][rh * 2 + 1]};
            F2 y2 = {acc[8 + v][rh * 2],  acc[8 + v][rh * 2 + 1]};
            F2 y3 = {acc[12 + v][rh * 2], acc[12 + v][rh * 2 + 1]};
            F2 s0 = f2add(y0, y2), s1 = f2add(y1, y3);
            F2 d0 = f2sub(y0, y2), d1 = f2sub(y1, y3);
            U[0][v] = f2add(s0, s1); U[1][v] = f2sub(s0, s1);
            U[2][v] = f2add(d0, d1); U[3][v] = f2sub(d0, d1);
        }
        #pragma unroll
        for (int p = 0; p < 4; p++) {
            F2 s0 = f2add(U[p][0], U[p][2]), s1 = f2add(U[p][1], U[p][3]);
            F2 d0 = f2sub(U[p][0], U[p][2]), d1 = f2sub(U[p][1], U[p][3]);
            F2 Z[4];
            Z[0] = f2add(s0, s1); Z[1] = f2sub(s0, s1);
            Z[2] = f2add(d0, d1); Z[3] = f2sub(d0, d1);
            float* orow = obase + (size_t)p * 7168;      // 112*64
            #pragma unroll
            for (int q = 0; q < 4; q++) {
                float zx = fmaf(Z[q].x, 0.0625f, bv.x);
                float zy = fmaf(Z[q].y, 0.0625f, bv.y);
                *(float2*)(orow + q * 64) = make_float2(zx, zy);
            }
        }
    }
}

// ---------------- launch ----------------
extern "C" void kernel_launch(void* const* d_in, const int* in_sizes, int n_in,
                              void* d_out, int out_size) {
    (void)in_sizes; (void)n_in; (void)out_size;
    const float* tr1 = (const float*)d_in[0];
    const float* tr2 = (const float*)d_in[1];
    const float* tr3 = (const float*)d_in[2];
    const float* w1  = (const float*)d_in[3];
    const float* w2  = (const float*)d_in[4];
    const float* w3  = (const float*)d_in[5];
    const float* b1  = (const float*)d_in[6];
    const float* b2  = (const float*)d_in[7];
    const float* b3  = (const float*)d_in[8];
    float* out = (float*)d_out;

    wprep_kernel<<<48, 256>>>(w1, w2, w3);
    dim3 grid(NBLK, 3);
    iwht_mma_kernel<<<grid, 256>>>(tr1, tr2, tr3, b1, b2, b3, out);
}

// round 10
// speedup vs baseline: 1.0301x; 1.0301x over previous
#include <cuda_runtime.h>
#include <cuda_fp16.h>
#include <cstdint>

// ---------------------------------------------------------------------------
// IWHT3Layer, round 10: v-split warp decomposition.
//   CTA: 256 threads / 8 warps / 16 pixels x 64 k x 1 branch, 2 CTAs/SM.
//   Warp (v=w&3, h=w>>2): owns t in {v, v+4, v+8, v+12} (all u for fixed v)
//   x n32 (k = 32h..32h+31).  acc[u][nbq][4] = 64 regs, ALL static indexing.
//   Phase 1: stage all 16 t A-tiles (f32 LDG bursts -> f16 smem), 1 barrier.
//   Phase 2: barrier-free MMA; ldmatrix traffic 4x lower than round 8
//            (each warp reads only its 4 t).
//   Epilogue: u-butterfly in regs -> U[p][v] exchanged via smem (overlaid on
//   dead A buffer, 2 p-passes) -> v-butterfly + bias -> coalesced float2 STG.
// ---------------------------------------------------------------------------

#define U32 unsigned int
#define U64 unsigned long long

static constexpr int PIXELS   = 12544;
static constexpr int PIX_CTA  = 16;
static constexpr int NBLK     = PIXELS / PIX_CTA;   // 784
static constexpr int T_STRIDE = PIXELS * 64;
static constexpr long long OPB = 16LL * 112 * 112 * 64;

static constexpr int A_PITCH  = 144;                 // conflict-free ldmatrix+STS
static constexpr int A_BUF    = 16 * A_PITCH;        // 2304 B per t
static constexpr int A_TOTAL  = 16 * A_BUF;          // 36864 B
static constexpr int U_PITCH  = 68;                  // floats; bank-rotating rows
// U pass region: 8 planes (2 p x 4 v) x 16 pix x 68 floats = 34816 B <= A_TOTAL

// B fragments: per (branch,t,nb,lane): 4 x U64 (kc 0..3) contiguous (32B)
__device__ __align__(16) U64 g_bfrag[3 * 16 * 8 * 32 * 4];

// ---------------- helpers ----------------
__device__ __forceinline__ U32 smem_u32(const void* p) {
    U32 a; asm("{ .reg .u64 t; cvta.to.shared.u64 t, %1; cvt.u32.u64 %0, t; }"
               : "=r"(a) : "l"(p)); return a;
}
__device__ __forceinline__ void ldm4(U32& a0, U32& a1, U32& a2, U32& a3, U32 addr) {
    asm volatile("ldmatrix.sync.aligned.m8n8.x4.shared.b16 {%0,%1,%2,%3}, [%4];"
                 : "=r"(a0), "=r"(a1), "=r"(a2), "=r"(a3) : "r"(addr));
}
__device__ __forceinline__ void mma16816(float* d, U32 a0, U32 a1, U32 a2, U32 a3,
                                         U32 b0, U32 b1) {
    asm volatile("mma.sync.aligned.m16n8k16.row.col.f32.f16.f16.f32 "
                 "{%0,%1,%2,%3}, {%4,%5,%6,%7}, {%8,%9}, {%0,%1,%2,%3};"
                 : "+f"(d[0]), "+f"(d[1]), "+f"(d[2]), "+f"(d[3])
                 : "r"(a0), "r"(a1), "r"(a2), "r"(a3), "r"(b0), "r"(b1));
}

// ---------------- prep: build fp16 B fragments (one-time) ----------------
__global__ void wprep_kernel(const float* __restrict__ w1,
                             const float* __restrict__ w2,
                             const float* __restrict__ w3) {
    int br = blockIdx.x >> 4, t = blockIdx.x & 15;
    const float* w = (br == 0 ? w1 : (br == 1 ? w2 : w3)) + t * 4096;
    __half* frag = (__half*)g_bfrag;
    for (int idx = threadIdx.x; idx < 4096; idx += blockDim.x) {
        int c = idx >> 6, k = idx & 63;          // w[c][k], coalesced over k
        __half h = __float2half(w[idx]);
        int kc = c >> 4, cw = c & 15;
        int nb = k >> 3, lane = (k & 7) * 4 + ((cw & 7) >> 1);
        int regj = cw >> 3, hlf = cw & 1;
        size_t u64i = ((((size_t)(br * 16 + t) * 8 + nb) * 32 + lane) * 4 + kc);
        frag[u64i * 4 + regj * 2 + hlf] = h;
    }
}

// ---------------- main kernel ----------------
__global__ __launch_bounds__(256, 2)
void iwht_mma_kernel(const float* __restrict__ tr1, const float* __restrict__ tr2,
                     const float* __restrict__ tr3,
                     const float* __restrict__ b1, const float* __restrict__ b2,
                     const float* __restrict__ b3,
                     float* __restrict__ out) {
    __shared__ __align__(16) char asm_buf[A_TOTAL];   // 36864 B
    float* const ubuf = (float*)asm_buf;              // overlay for U exchange

    const int tid  = threadIdx.x;
    const int lane = tid & 31;
    const int w    = tid >> 5;     // 0..7
    const int v    = w & 3;        // WHT column coefficient group
    const int h    = w >> 2;       // n-half (k 0..31 / 32..63)

    const int branch = blockIdx.y;
    const float* tr   = (branch == 0 ? tr1 : (branch == 1 ? tr2 : tr3));
    const float* bias = (branch == 0 ? b1  : (branch == 1 ? b2  : b3));
    const int pix0 = blockIdx.x * PIX_CTA;

    // ---------------- phase 1: stage all 16 t ----------------
    {
        const int crow = tid >> 4, cseg = tid & 15;
        const float* xrow = tr + (size_t)(pix0 + crow) * 64 + cseg * 4;
        char* sdst = asm_buf + crow * A_PITCH + cseg * 8;
        #pragma unroll
        for (int b = 0; b < 2; b++) {
            float4 xv[8];
            #pragma unroll
            for (int j = 0; j < 8; j++)
                xv[j] = *(const float4*)(xrow + (size_t)(b * 8 + j) * T_STRIDE);
            #pragma unroll
            for (int j = 0; j < 8; j++) {
                __half2 h0 = __floats2half2_rn(xv[j].x, xv[j].y);
                __half2 h1 = __floats2half2_rn(xv[j].z, xv[j].w);
                *(uint2*)(sdst + (b * 8 + j) * A_BUF) =
                    make_uint2(*reinterpret_cast<U32*>(&h0),
                               *reinterpret_cast<U32*>(&h1));
            }
        }
    }
    __syncthreads();

    // ---------------- phase 2: barrier-free MMA (warp owns 4 t, n32) -------
    const U32 sbase = smem_u32(asm_buf);
    const U32 arow0 = sbase + (U32)((lane & 15) * A_PITCH + (lane >> 4) * 16);
    const U64* gbase = g_bfrag + (size_t)branch * 16 * 8 * 32 * 4;

    float acc[4][4][4];            // [u][nbq][i] -- all STATIC indexing
    #pragma unroll
    for (int u = 0; u < 4; u++)
        #pragma unroll
        for (int n = 0; n < 4; n++)
            #pragma unroll
            for (int i = 0; i < 4; i++) acc[u][n][i] = 0.0f;

    #pragma unroll
    for (int u = 0; u < 4; u++) {
        const int t = 4 * u + v;
        U32 af[4][4];
        #pragma unroll
        for (int kc = 0; kc < 4; kc++)
            ldm4(af[kc][0], af[kc][1], af[kc][2], af[kc][3],
                 arow0 + (U32)(t * A_BUF + kc * 32));
        #pragma unroll
        for (int nbq = 0; nbq < 4; nbq++) {
            const uint4* bp = (const uint4*)(gbase +
                (((size_t)t * 8 + h * 4 + nbq) * 32 + lane) * 4);
            uint4 bv0 = bp[0], bv1 = bp[1];
            U32 bb[8] = { bv0.x, bv0.y, bv0.z, bv0.w, bv1.x, bv1.y, bv1.z, bv1.w };
            #pragma unroll
            for (int kc = 0; kc < 4; kc++)
                mma16816(acc[u][nbq], af[kc][0], af[kc][1], af[kc][2], af[kc][3],
                         bb[kc * 2], bb[kc * 2 + 1]);
        }
    }

    // ---------------- epilogue: 2-pass U exchange + v-butterfly ------------
    const int cl = lane & 3, rl = lane >> 2;
    float* const outB = out + (size_t)branch * OPB;
    const float2 bvv = *(const float2*)(bias + 2 * lane);

    // per-unit output addressing (pix = w + 8r, k = 2*lane)
    int opix[2]; size_t obase[2];
    #pragma unroll
    for (int r = 0; r < 2; r++) {
        const int pix = w + 8 * r;
        const int P = pix0 + pix;
        const int pb_ = P / 784, rr = P - pb_ * 784;
        const int ii = rr / 28, jj = rr - ii * 28;
        opix[r] = pix;
        obase[r] = ((size_t)(pb_ * 112 + ii * 4) * 112 + jj * 4) * 64 + 2 * lane;
    }

    #pragma unroll
    for (int pp = 0; pp < 2; pp++) {
        __syncthreads();    // pass 0: all ldmatrix done; pass 1: all reads done

        // write planes (p = 2*pp + pl, this warp's v), u-butterfly in regs
        #pragma unroll
        for (int nbq = 0; nbq < 4; nbq++) {
            float Up[2][4];
            #pragma unroll
            for (int i = 0; i < 4; i++) {
                float y0 = acc[0][nbq][i], y1 = acc[1][nbq][i];
                float y2 = acc[2][nbq][i], y3 = acc[3][nbq][i];
                if (pp == 0) {
                    float s0 = y0 + y2, s1 = y1 + y3;
                    Up[0][i] = s0 + s1;      // p=0
                    Up[1][i] = s0 - s1;      // p=1
                } else {
                    float d0 = y0 - y2, d1 = y1 - y3;
                    Up[0][i] = d0 + d1;      // p=2
                    Up[1][i] = d0 - d1;      // p=3
                }
            }
            const int kcol = h * 32 + nbq * 8 + 2 * cl;
            #pragma unroll
            for (int pl = 0; pl < 2; pl++) {
                int base = ((pl * 4 + v) * 16 + rl) * U_PITCH + kcol;
                *(float2*)(ubuf + base)              = make_float2(Up[pl][0], Up[pl][1]);
                *(float2*)(ubuf + base + 8 * U_PITCH) = make_float2(Up[pl][2], Up[pl][3]);
            }
        }
        __syncthreads();

        // read + v-butterfly + store (unit: pix = w + 8r, k = 2*lane)
        #pragma unroll
        for (int r = 0; r < 2; r++) {
            #pragma unroll
            for (int pl = 0; pl < 2; pl++) {
                float2 Uv[4];
                #pragma unroll
                for (int vv = 0; vv < 4; vv++)
                    Uv[vv] = *(const float2*)(ubuf +
                        ((pl * 4 + vv) * 16 + opix[r]) * U_PITCH + 2 * lane);
                float2 s0 = make_float2(Uv[0].x + Uv[2].x, Uv[0].y + Uv[2].y);
                float2 s1 = make_float2(Uv[1].x + Uv[3].x, Uv[1].y + Uv[3].y);
                float2 d0 = make_float2(Uv[0].x - Uv[2].x, Uv[0].y - Uv[2].y);
                float2 d1 = make_float2(Uv[1].x - Uv[3].x, Uv[1].y - Uv[3].y);
                float2 Z[4];
                Z[0] = make_float2(s0.x + s1.x, s0.y + s1.y);
                Z[1] = make_float2(s0.x - s1.x, s0.y - s1.y);
                Z[2] = make_float2(d0.x + d1.x, d0.y + d1.y);
                Z[3] = make_float2(d0.x - d1.x, d0.y - d1.y);
                const int p = pp * 2 + pl;
                float* orow = outB + obase[r] + (size_t)p * 7168;   // p*112*64
                #pragma unroll
                for (int q = 0; q < 4; q++) {
                    float zx = fmaf(Z[q].x, 0.0625f, bvv.x);
                    float zy = fmaf(Z[q].y, 0.0625f, bvv.y);
                    *(float2*)(orow + q * 64) = make_float2(zx, zy);
                }
            }
        }
    }
}

// ---------------- launch ----------------
extern "C" void kernel_launch(void* const* d_in, const int* in_sizes, int n_in,
                              void* d_out, int out_size) {
    (void)in_sizes; (void)n_in; (void)out_size;
    const float* tr1 = (const float*)d_in[0];
    const float* tr2 = (const float*)d_in[1];
    const float* tr3 = (const float*)d_in[2];
    const float* w1  = (const float*)d_in[3];
    const float* w2  = (const float*)d_in[4];
    const float* w3  = (const float*)d_in[5];
    const float* b1  = (const float*)d_in[6];
    const float* b2  = (const float*)d_in[7];
    const float* b3  = (const float*)d_in[8];
    float* out = (float*)d_out;

    wprep_kernel<<<48, 256>>>(w1, w2, w3);
    dim3 grid(NBLK, 3);
    iwht_mma_kernel<<<grid, 256>>>(tr1, tr2, tr3, b1, b2, b3, out);
}

// round 11
// speedup vs baseline: 1.3436x; 1.3043x over previous
#include <cuda_runtime.h>
#include <cuda_fp16.h>
#include <cstdint>

// ---------------------------------------------------------------------------
// IWHT3Layer, round 11: round-8 dataflow with PAIR staging (8 barriers).
//   CTA: 256 threads / 8 warps / 16 pixels x 64 k x 1 branch, 2 CTAs/SM.
//   Warp w: m16 x n8 (k = 8w..8w+7), ALL 16 t in regs (acc[16][4]).
//   4-slot A buffer (slot = t & 3): window i reads slots {2i,2i+1}&3 and
//   stages x(2i+2),x(2i+3) into the other two -> disjoint, 1 barrier/pair.
//   x LDG issued at window top (~full window to cover DRAM latency).
//   B prepacked fragments, 2x LDG.128 per t, register double-buffered.
//   Epilogue: in-register 2D WHT butterflies + bias + float2 stores.
// ---------------------------------------------------------------------------

#define U32 unsigned int
#define U64 unsigned long long

static constexpr int PIXELS   = 12544;
static constexpr int PIX_CTA  = 16;
static constexpr int NBLK     = PIXELS / PIX_CTA;   // 784
static constexpr int T_STRIDE = PIXELS * 64;
static constexpr long long OPB = 16LL * 112 * 112 * 64;

static constexpr int A_PITCH  = 144;                 // conflict-free ldmatrix+STS
static constexpr int A_BUF    = 16 * A_PITCH;        // 2304 B per slot
// 4 slots = 9216 B

// B fragments: per (branch,t,nb,lane): 4 x U64 (kc 0..3) contiguous (32B)
__device__ __align__(16) U64 g_bfrag[3 * 16 * 8 * 32 * 4];

// ---------------- helpers ----------------
__device__ __forceinline__ U32 smem_u32(const void* p) {
    U32 a; asm("{ .reg .u64 t; cvta.to.shared.u64 t, %1; cvt.u32.u64 %0, t; }"
               : "=r"(a) : "l"(p)); return a;
}
__device__ __forceinline__ void ldm4(U32& a0, U32& a1, U32& a2, U32& a3, U32 addr) {
    asm volatile("ldmatrix.sync.aligned.m8n8.x4.shared.b16 {%0,%1,%2,%3}, [%4];"
                 : "=r"(a0), "=r"(a1), "=r"(a2), "=r"(a3) : "r"(addr));
}
__device__ __forceinline__ void mma16816(float* d, U32 a0, U32 a1, U32 a2, U32 a3,
                                         U32 b0, U32 b1) {
    asm volatile("mma.sync.aligned.m16n8k16.row.col.f32.f16.f16.f32 "
                 "{%0,%1,%2,%3}, {%4,%5,%6,%7}, {%8,%9}, {%0,%1,%2,%3};"
                 : "+f"(d[0]), "+f"(d[1]), "+f"(d[2]), "+f"(d[3])
                 : "r"(a0), "r"(a1), "r"(a2), "r"(a3), "r"(b0), "r"(b1));
}
struct F2 { float x, y; };
__device__ __forceinline__ F2 f2add(F2 a, F2 b) { return {a.x + b.x, a.y + b.y}; }
__device__ __forceinline__ F2 f2sub(F2 a, F2 b) { return {a.x - b.x, a.y - b.y}; }

// ---------------- prep: build fp16 B fragments (one-time) ----------------
__global__ void wprep_kernel(const float* __restrict__ w1,
                             const float* __restrict__ w2,
                             const float* __restrict__ w3) {
    int br = blockIdx.x >> 4, t = blockIdx.x & 15;
    const float* w = (br == 0 ? w1 : (br == 1 ? w2 : w3)) + t * 4096;
    __half* frag = (__half*)g_bfrag;
    for (int idx = threadIdx.x; idx < 4096; idx += blockDim.x) {
        int c = idx >> 6, k = idx & 63;          // w[c][k], coalesced over k
        __half h = __float2half(w[idx]);
        int kc = c >> 4, cw = c & 15;
        int nb = k >> 3, lane = (k & 7) * 4 + ((cw & 7) >> 1);
        int regj = cw >> 3, hlf = cw & 1;
        size_t u64i = ((((size_t)(br * 16 + t) * 8 + nb) * 32 + lane) * 4 + kc);
        frag[u64i * 4 + regj * 2 + hlf] = h;
    }
}

// ---------------- main kernel ----------------
__global__ __launch_bounds__(256, 2)
void iwht_mma_kernel(const float* __restrict__ tr1, const float* __restrict__ tr2,
                     const float* __restrict__ tr3,
                     const float* __restrict__ b1, const float* __restrict__ b2,
                     const float* __restrict__ b3,
                     float* __restrict__ out) {
    __shared__ __align__(16) char asm_buf[4 * A_BUF];   // 9216 B, 4 slots

    const int tid  = threadIdx.x;
    const int lane = tid & 31;
    const int w    = tid >> 5;     // 0..7 -> n8 block (k outputs)

    const int branch = blockIdx.y;
    const float* tr   = (branch == 0 ? tr1 : (branch == 1 ? tr2 : tr3));
    const float* bias = (branch == 0 ? b1  : (branch == 1 ? b2  : b3));
    const int pix0 = blockIdx.x * PIX_CTA;

    // staging role: thread -> (row 0..15, 4 floats at cseg*4)
    const int crow = tid >> 4, cseg = tid & 15;
    const float* xrow = tr + (size_t)(pix0 + crow) * 64 + cseg * 4;

    auto cvtStore = [&](float4 a, int slot) {
        __half2 h0 = __floats2half2_rn(a.x, a.y);
        __half2 h1 = __floats2half2_rn(a.z, a.w);
        *(uint2*)(asm_buf + slot * A_BUF + crow * A_PITCH + cseg * 8) =
            make_uint2(*reinterpret_cast<U32*>(&h0), *reinterpret_cast<U32*>(&h1));
    };

    // B fragments: 32B contiguous per (t, warp, lane)
    const U64* gb = g_bfrag + (((size_t)branch * 16 * 8 + w) * 32 + lane) * 4;
    auto loadB = [&](int t, U64* dst) {
        const uint4* p = (const uint4*)(gb + (size_t)t * 8 * 32 * 4);
        uint4 v0 = p[0], v1 = p[1];
        dst[0] = (U64)v0.x | ((U64)v0.y << 32);
        dst[1] = (U64)v0.z | ((U64)v0.w << 32);
        dst[2] = (U64)v1.x | ((U64)v1.y << 32);
        dst[3] = (U64)v1.z | ((U64)v1.w << 32);
    };

    // prologue: stage t=0,1 (synchronous), prefetch B(0)
    cvtStore(*(const float4*)xrow, 0);
    cvtStore(*(const float4*)(xrow + T_STRIDE), 1);
    U64 bcur[4], bnxt[4];
    loadB(0, bcur);
    __syncthreads();

    const U32 sbase = smem_u32(asm_buf);
    const U32 arow0 = sbase + (U32)((lane & 15) * A_PITCH + (lane >> 4) * 16);

    float acc[16][4];
    #pragma unroll
    for (int t = 0; t < 16; t++)
        #pragma unroll
        for (int i = 0; i < 4; i++) acc[t][i] = 0.0f;

    #pragma unroll
    for (int i = 0; i < 8; i++) {
        const int t0 = 2 * i;

        // x prefetch for next pair -- issued at window top, lands over window
        float4 pa0, pa1;
        if (i < 7) {
            pa0 = *(const float4*)(xrow + (size_t)(t0 + 2) * T_STRIDE);
            pa1 = *(const float4*)(xrow + (size_t)(t0 + 3) * T_STRIDE);
        }

        // ---- t0 ----
        loadB(t0 + 1, bnxt);                        // L2-hot, lands over MMAs
        {
            const U32 ab = arow0 + (U32)((t0 & 3) * A_BUF);
            #pragma unroll
            for (int kc = 0; kc < 4; kc++) {
                U32 a0, a1, a2, a3;
                ldm4(a0, a1, a2, a3, ab + kc * 32);
                mma16816(acc[t0], a0, a1, a2, a3,
                         (U32)bcur[kc], (U32)(bcur[kc] >> 32));
            }
        }
        #pragma unroll
        for (int kc = 0; kc < 4; kc++) bcur[kc] = bnxt[kc];

        // ---- t0+1 ----
        if (i < 7) loadB(t0 + 2, bnxt);
        {
            const U32 ab = arow0 + (U32)(((t0 + 1) & 3) * A_BUF);
            #pragma unroll
            for (int kc = 0; kc < 4; kc++) {
                U32 a0, a1, a2, a3;
                ldm4(a0, a1, a2, a3, ab + kc * 32);
                mma16816(acc[t0 + 1], a0, a1, a2, a3,
                         (U32)bcur[kc], (U32)(bcur[kc] >> 32));
            }
        }
        #pragma unroll
        for (int kc = 0; kc < 4; kc++) bcur[kc] = bnxt[kc];

        // stage next pair into the other two slots
        if (i < 7) {
            cvtStore(pa0, (t0 + 2) & 3);
            cvtStore(pa1, (t0 + 3) & 3);
        }
        __syncthreads();
    }

    // ---------------- epilogue: in-register 2D WHT + bias + stores ----------
    const int cl = lane & 3, rl = lane >> 2;
    float* outB = out + (size_t)branch * OPB;
    const int kst = w * 8 + cl * 2;
    const float2 bv = *(const float2*)(bias + kst);

    #pragma unroll
    for (int rh = 0; rh < 2; rh++) {
        const int P = pix0 + rh * 8 + rl;
        const int pb_ = P / 784, rr = P - pb_ * 784;
        const int ii = rr / 28, jj = rr - ii * 28;
        float* obase = outB + ((size_t)(pb_ * 112 + ii * 4) * 112 + jj * 4) * 64 + kst;

        // u-stage butterflies over t = 4u+v
        F2 U[4][4];
        #pragma unroll
        for (int v = 0; v < 4; v++) {
            F2 y0 = {acc[v][rh * 2],      acc[v][rh * 2 + 1]};
            F2 y1 = {acc[4 + v][rh * 2],  acc[4 + v][rh * 2 + 1]};
            F2 y2 = {acc[8 + v][rh * 2],  acc[8 + v][rh * 2 + 1]};
            F2 y3 = {acc[12 + v][rh * 2], acc[12 + v][rh * 2 + 1]};
            F2 s0 = f2add(y0, y2), s1 = f2add(y1, y3);
            F2 d0 = f2sub(y0, y2), d1 = f2sub(y1, y3);
            U[0][v] = f2add(s0, s1); U[1][v] = f2sub(s0, s1);
            U[2][v] = f2add(d0, d1); U[3][v] = f2sub(d0, d1);
        }
        #pragma unroll
        for (int p = 0; p < 4; p++) {
            F2 s0 = f2add(U[p][0], U[p][2]), s1 = f2add(U[p][1], U[p][3]);
            F2 d0 = f2sub(U[p][0], U[p][2]), d1 = f2sub(U[p][1], U[p][3]);
            F2 Z[4];
            Z[0] = f2add(s0, s1); Z[1] = f2sub(s0, s1);
            Z[2] = f2add(d0, d1); Z[3] = f2sub(d0, d1);
            float* orow = obase + (size_t)p * 7168;      // 112*64
            #pragma unroll
            for (int q = 0; q < 4; q++) {
                float zx = fmaf(Z[q].x, 0.0625f, bv.x);
                float zy = fmaf(Z[q].y, 0.0625f, bv.y);
                *(float2*)(orow + q * 64) = make_float2(zx, zy);
            }
        }
    }
}

// ---------------- launch ----------------
extern "C" void kernel_launch(void* const* d_in, const int* in_sizes, int n_in,
                              void* d_out, int out_size) {
    (void)in_sizes; (void)n_in; (void)out_size;
    const float* tr1 = (const float*)d_in[0];
    const float* tr2 = (const float*)d_in[1];
    const float* tr3 = (const float*)d_in[2];
    const float* w1  = (const float*)d_in[3];
    const float* w2  = (const float*)d_in[4];
    const float* w3  = (const float*)d_in[5];
    const float* b1  = (const float*)d_in[6];
    const float* b2  = (const float*)d_in[7];
    const float* b3  = (const float*)d_in[8];
    float* out = (float*)d_out;

    wprep_kernel<<<48, 256>>>(w1, w2, w3);
    dim3 grid(NBLK, 3);
    iwht_mma_kernel<<<grid, 256>>>(tr1, tr2, tr3, b1, b2, b3, out);
}

// round 12
// speedup vs baseline: 1.5100x; 1.1238x over previous
#include <cuda_runtime.h>
#include <cuda_fp16.h>
#include <cstdint>

// ---------------------------------------------------------------------------
// IWHT3Layer, round 12: round-8 dataflow + 2-deep x register prefetch.
//   CTA: 256 threads / 8 warps / 16 pixels x 64 k x 1 branch, 2 CTAs/SM.
//   Warp w: m16 x n8 (k = 8w..8w+7), ALL 16 t in regs (acc[16][4]).
//   Window t: LDG x(t+2) -> pa[t&1]   (consumed end of t+1: ~1.5 windows)
//             loadB(t+1) -> bbuf[(t+1)&1]            (L2-hot, 1 window)
//             4x ldmatrix + 4x MMA on slot t&1, bbuf[t&1]
//             cvtStore x(t+1) -> slot (t+1)&1 ; __syncthreads.
//   Epilogue: in-register 2D WHT butterflies + bias + float2 stores.
//   wprep: coalesced-store repack (1 thread per dst U64), 192 blocks.
// ---------------------------------------------------------------------------

#define U32 unsigned int
#define U64 unsigned long long

static constexpr int PIXELS   = 12544;
static constexpr int PIX_CTA  = 16;
static constexpr int NBLK     = PIXELS / PIX_CTA;   // 784
static constexpr int T_STRIDE = PIXELS * 64;
static constexpr long long OPB = 16LL * 112 * 112 * 64;

static constexpr int A_PITCH  = 144;                 // conflict-free ldmatrix+STS
static constexpr int A_BUF    = 16 * A_PITCH;        // 2304 B per buffer

// B fragments: per (branch,t,nb,lane): 4 x U64 (kc 0..3) contiguous (32B)
__device__ __align__(16) U64 g_bfrag[3 * 16 * 8 * 32 * 4];   // 49152 u64

// ---------------- helpers ----------------
__device__ __forceinline__ U32 smem_u32(const void* p) {
    U32 a; asm("{ .reg .u64 t; cvta.to.shared.u64 t, %1; cvt.u32.u64 %0, t; }"
               : "=r"(a) : "l"(p)); return a;
}
__device__ __forceinline__ void ldm4(U32& a0, U32& a1, U32& a2, U32& a3, U32 addr) {
    asm volatile("ldmatrix.sync.aligned.m8n8.x4.shared.b16 {%0,%1,%2,%3}, [%4];"
                 : "=r"(a0), "=r"(a1), "=r"(a2), "=r"(a3) : "r"(addr));
}
__device__ __forceinline__ void mma16816(float* d, U32 a0, U32 a1, U32 a2, U32 a3,
                                         U32 b0, U32 b1) {
    asm volatile("mma.sync.aligned.m16n8k16.row.col.f32.f16.f16.f32 "
                 "{%0,%1,%2,%3}, {%4,%5,%6,%7}, {%8,%9}, {%0,%1,%2,%3};"
                 : "+f"(d[0]), "+f"(d[1]), "+f"(d[2]), "+f"(d[3])
                 : "r"(a0), "r"(a1), "r"(a2), "r"(a3), "r"(b0), "r"(b1));
}
struct F2 { float x, y; };
__device__ __forceinline__ F2 f2add(F2 a, F2 b) { return {a.x + b.x, a.y + b.y}; }
__device__ __forceinline__ F2 f2sub(F2 a, F2 b) { return {a.x - b.x, a.y - b.y}; }

// ---------------- prep: coalesced-store fragment repack ----------------
// one thread per dst U64: gid -> (br,t,nb,lane,kc); gathers w[t][c][k] for
// c = kc*16 + {0,1,8,9} + 2*(lane&3), k = nb*8 + (lane>>2).
__global__ void wprep_kernel(const float* __restrict__ w1,
                             const float* __restrict__ w2,
                             const float* __restrict__ w3) {
    int gid = blockIdx.x * 256 + threadIdx.x;           // 0..49151
    int kc   = gid & 3;
    int lane = (gid >> 2) & 31;
    int nb   = (gid >> 7) & 7;
    int t    = (gid >> 10) & 15;
    int br   = gid >> 14;
    const float* w = (br == 0 ? w1 : (br == 1 ? w2 : w3)) + t * 4096;
    int k  = nb * 8 + (lane >> 2);
    int cb = kc * 16 + 2 * (lane & 3);
    __half h0 = __float2half(w[(cb)     * 64 + k]);
    __half h1 = __float2half(w[(cb + 1) * 64 + k]);
    __half h2 = __float2half(w[(cb + 8) * 64 + k]);
    __half h3 = __float2half(w[(cb + 9) * 64 + k]);
    U32 lo = ((U32)__half_as_ushort(h1) << 16) | __half_as_ushort(h0);
    U32 hi = ((U32)__half_as_ushort(h3) << 16) | __half_as_ushort(h2);
    g_bfrag[gid] = (U64)lo | ((U64)hi << 32);
}

// ---------------- main kernel ----------------
__global__ __launch_bounds__(256, 2)
void iwht_mma_kernel(const float* __restrict__ tr1, const float* __restrict__ tr2,
                     const float* __restrict__ tr3,
                     const float* __restrict__ b1, const float* __restrict__ b2,
                     const float* __restrict__ b3,
                     float* __restrict__ out) {
    __shared__ __align__(16) char asm_buf[2 * A_BUF];   // 4608 B

    const int tid  = threadIdx.x;
    const int lane = tid & 31;
    const int w    = tid >> 5;     // 0..7 -> n8 block (k outputs)

    const int branch = blockIdx.y;
    const float* tr   = (branch == 0 ? tr1 : (branch == 1 ? tr2 : tr3));
    const float* bias = (branch == 0 ? b1  : (branch == 1 ? b2  : b3));
    const int pix0 = blockIdx.x * PIX_CTA;

    // staging role: thread -> (row 0..15, 4 floats at cseg*4)
    const int crow = tid >> 4, cseg = tid & 15;
    const float* xrow = tr + (size_t)(pix0 + crow) * 64 + cseg * 4;

    auto cvtStore = [&](float4 a, int buf) {
        __half2 h0 = __floats2half2_rn(a.x, a.y);
        __half2 h1 = __floats2half2_rn(a.z, a.w);
        *(uint2*)(asm_buf + buf * A_BUF + crow * A_PITCH + cseg * 8) =
            make_uint2(*reinterpret_cast<U32*>(&h0), *reinterpret_cast<U32*>(&h1));
    };

    // B fragments: 32B contiguous per (t, warp, lane)
    const U64* gb = g_bfrag + (((size_t)branch * 16 * 8 + w) * 32 + lane) * 4;
    auto loadB = [&](int t, U64* dst) {
        const uint4* p = (const uint4*)(gb + (size_t)t * 8 * 32 * 4);
        uint4 v0 = p[0], v1 = p[1];
        dst[0] = (U64)v0.x | ((U64)v0.y << 32);
        dst[1] = (U64)v0.z | ((U64)v0.w << 32);
        dst[2] = (U64)v1.x | ((U64)v1.y << 32);
        dst[3] = (U64)v1.z | ((U64)v1.w << 32);
    };

    // prologue: stage t=0; x(1) into pa[1]; B(0) into bbuf[0]
    float4 pa[2];
    U64 bbuf[2][4];
    cvtStore(*(const float4*)xrow, 0);
    pa[1] = *(const float4*)(xrow + T_STRIDE);
    loadB(0, bbuf[0]);
    __syncthreads();

    const U32 sbase = smem_u32(asm_buf);
    const U32 arow0 = sbase + (U32)((lane & 15) * A_PITCH + (lane >> 4) * 16);

    float acc[16][4];
    #pragma unroll
    for (int t = 0; t < 16; t++)
        #pragma unroll
        for (int i = 0; i < 4; i++) acc[t][i] = 0.0f;

    #pragma unroll
    for (int t = 0; t < 16; t++) {
        // deep x prefetch: x(t+2) lands ~1.5 windows later
        if (t < 14)
            pa[t & 1] = *(const float4*)(xrow + (size_t)(t + 2) * T_STRIDE);
        // B(t+1): L2-hot, 1 window ahead
        if (t < 15)
            loadB(t + 1, bbuf[(t + 1) & 1]);

        // MMAs for t
        const U32 ab = arow0 + (U32)((t & 1) * A_BUF);
        #pragma unroll
        for (int kc = 0; kc < 4; kc++) {
            U32 a0, a1, a2, a3;
            ldm4(a0, a1, a2, a3, ab + kc * 32);
            mma16816(acc[t], a0, a1, a2, a3,
                     (U32)bbuf[t & 1][kc], (U32)(bbuf[t & 1][kc] >> 32));
        }

        // stage A(t+1) from pa (loaded at window t-1)
        if (t < 15) cvtStore(pa[(t + 1) & 1], (t + 1) & 1);
        __syncthreads();
    }

    // ---------------- epilogue: in-register 2D WHT + bias + stores ----------
    const int cl = lane & 3, rl = lane >> 2;
    float* outB = out + (size_t)branch * OPB;
    const int kst = w * 8 + cl * 2;
    const float2 bv = *(const float2*)(bias + kst);

    #pragma unroll
    for (int rh = 0; rh < 2; rh++) {
        const int P = pix0 + rh * 8 + rl;
        const int pb_ = P / 784, rr = P - pb_ * 784;
        const int ii = rr / 28, jj = rr - ii * 28;
        float* obase = outB + ((size_t)(pb_ * 112 + ii * 4) * 112 + jj * 4) * 64 + kst;

        // u-stage butterflies over t = 4u+v
        F2 U[4][4];
        #pragma unroll
        for (int v = 0; v < 4; v++) {
            F2 y0 = {acc[v][rh * 2],      acc[v][rh * 2 + 1]};
            F2 y1 = {acc[4 + v][rh * 2],  acc[4 + v][rh * 2 + 1]};
            F2 y2 = {acc[8 + v][rh * 2],  acc[8 + v][rh * 2 + 1]};
            F2 y3 = {acc[12 + v][rh * 2], acc[12 + v][rh * 2 + 1]};
            F2 s0 = f2add(y0, y2), s1 = f2add(y1, y3);
            F2 d0 = f2sub(y0, y2), d1 = f2sub(y1, y3);
            U[0][v] = f2add(s0, s1); U[1][v] = f2sub(s0, s1);
            U[2][v] = f2add(d0, d1); U[3][v] = f2sub(d0, d1);
        }
        #pragma unroll
        for (int p = 0; p < 4; p++) {
            F2 s0 = f2add(U[p][0], U[p][2]), s1 = f2add(U[p][1], U[p][3]);
            F2 d0 = f2sub(U[p][0], U[p][2]), d1 = f2sub(U[p][1], U[p][3]);
            F2 Z[4];
            Z[0] = f2add(s0, s1); Z[1] = f2sub(s0, s1);
            Z[2] = f2add(d0, d1); Z[3] = f2sub(d0, d1);
            float* orow = obase + (size_t)p * 7168;      // 112*64
            #pragma unroll
            for (int q = 0; q < 4; q++) {
                float zx = fmaf(Z[q].x, 0.0625f, bv.x);
                float zy = fmaf(Z[q].y, 0.0625f, bv.y);
                *(float2*)(orow + q * 64) = make_float2(zx, zy);
            }
        }
    }
}

// ---------------- launch ----------------
extern "C" void kernel_launch(void* const* d_in, const int* in_sizes, int n_in,
                              void* d_out, int out_size) {
    (void)in_sizes; (void)n_in; (void)out_size;
    const float* tr1 = (const float*)d_in[0];
    const float* tr2 = (const float*)d_in[1];
    const float* tr3 = (const float*)d_in[2];
    const float* w1  = (const float*)d_in[3];
    const float* w2  = (const float*)d_in[4];
    const float* w3  = (const float*)d_in[5];
    const float* b1  = (const float*)d_in[6];
    const float* b2  = (const float*)d_in[7];
    const float* b3  = (const float*)d_in[8];
    float* out = (float*)d_out;

    wprep_kernel<<<192, 256>>>(w1, w2, w3);
    dim3 grid(NBLK, 3);
    iwht_mma_kernel<<<grid, 256>>>(tr1, tr2, tr3, b1, b2, b3, out);
}